// round 15
// baseline (speedup 1.0000x reference)
#include <cuda_runtime.h>
#include <cuda_bf16.h>
#include <cstdint>

#define BS 2
#define SEQ 2048
#define DMODEL 1024
#define NHEADS 16
#define DEPTH 64
#define BH (BS*NHEADS)
#define MTOT (BS*SEQ)
#define SA 40    // bf16 smem row stride
#define SAF 40   // fp32 smem row stride

// ---------------------------------------------------------------------------
// Device scratch
// ---------------------------------------------------------------------------
__device__ __nv_bfloat16 g_xhi[3ULL*MTOT*DMODEL], g_xlo[3ULL*MTOT*DMODEL];
__device__ __nv_bfloat16 g_wThi[4ULL*DMODEL*DMODEL], g_wTlo[4ULL*DMODEL*DMODEL];
__device__ __nv_bfloat16 g_qhi[(size_t)BH*SEQ*DEPTH], g_qlo[(size_t)BH*SEQ*DEPTH];
__device__ __nv_bfloat16 g_khi[(size_t)BH*SEQ*DEPTH], g_klo[(size_t)BH*SEQ*DEPTH];
__device__ __nv_bfloat16 g_vhi[(size_t)BH*SEQ*DEPTH], g_vlo[(size_t)BH*SEQ*DEPTH];
__device__ __nv_bfloat16 g_vThi[(size_t)BH*DEPTH*SEQ], g_vTlo[(size_t)BH*DEPTH*SEQ];
__device__ __nv_bfloat16 g_athi[(size_t)MTOT*DMODEL], g_atlo[(size_t)MTOT*DMODEL];
__device__ float g_E[(size_t)BH*SEQ*SEQ];       // unnormalized exp(scores)
__device__ float g_rowsum[(size_t)BH*SEQ];

// ---------------------------------------------------------------------------
__device__ __forceinline__ void split_bf16(float x, __nv_bfloat16& h, __nv_bfloat16& l) {
    h = __float2bfloat16(x);
    l = __float2bfloat16(x - __bfloat162float(h));
}

__device__ __forceinline__ void split2(float2 f, uint32_t& hi, uint32_t& lo) {
    __nv_bfloat162 h = __float22bfloat162_rn(f);
    float2 r;
    r.x = f.x - __bfloat162float(h.x);
    r.y = f.y - __bfloat162float(h.y);
    __nv_bfloat162 l = __float22bfloat162_rn(r);
    hi = *reinterpret_cast<uint32_t*>(&h);
    lo = *reinterpret_cast<uint32_t*>(&l);
}

__device__ __forceinline__ void mma_bf16(float c[4],
        uint32_t a0, uint32_t a1, uint32_t a2, uint32_t a3,
        uint32_t b0, uint32_t b1) {
    asm volatile(
        "mma.sync.aligned.m16n8k16.row.col.f32.bf16.bf16.f32 "
        "{%0,%1,%2,%3}, {%4,%5,%6,%7}, {%8,%9}, {%0,%1,%2,%3};"
        : "+f"(c[0]), "+f"(c[1]), "+f"(c[2]), "+f"(c[3])
        : "r"(a0), "r"(a1), "r"(a2), "r"(a3), "r"(b0), "r"(b1));
}

__device__ __forceinline__ uint32_t ld32(const __nv_bfloat16* p) {
    return *reinterpret_cast<const uint32_t*>(p);
}

__device__ __forceinline__ uint32_t smem_u32(const void* p) {
    uint32_t a;
    asm("{ .reg .u64 t; cvta.to.shared.u64 t, %1; cvt.u32.u64 %0, t; }" : "=r"(a) : "l"(p));
    return a;
}
__device__ __forceinline__ void cp16(uint32_t dst, const void* src) {
    asm volatile("cp.async.cg.shared.global [%0], [%1], 16;" :: "r"(dst), "l"(src));
}
#define CP_COMMIT() asm volatile("cp.async.commit_group;" ::: "memory")
#define CP_WAIT(n)  asm volatile("cp.async.wait_group %0;" :: "n"(n) : "memory")

// ---------------------------------------------------------------------------
// Prep kernels
// ---------------------------------------------------------------------------
__global__ void prep_inputs(const float* __restrict__ q, const float* __restrict__ k,
                            const float* __restrict__ v) {
    const size_t n1 = (size_t)MTOT * DMODEL;
    const size_t n1v = n1 / 4;
    size_t total = 3 * n1v;
    for (size_t i = blockIdx.x * (size_t)blockDim.x + threadIdx.x; i < total;
         i += (size_t)gridDim.x * blockDim.x) {
        size_t seg = i / n1v;
        size_t off = (i - seg * n1v) * 4;
        const float* src = (seg == 0) ? q : (seg == 1) ? k : v;
        float4 f = *(const float4*)(src + off);
        size_t base = seg * n1 + off;
        __nv_bfloat16 h, l;
        split_bf16(f.x, h, l); g_xhi[base+0] = h; g_xlo[base+0] = l;
        split_bf16(f.y, h, l); g_xhi[base+1] = h; g_xlo[base+1] = l;
        split_bf16(f.z, h, l); g_xhi[base+2] = h; g_xlo[base+2] = l;
        split_bf16(f.w, h, l); g_xhi[base+3] = h; g_xlo[base+3] = l;
    }
}

__global__ void prep_weights(const float* __restrict__ Wq, const float* __restrict__ Wk,
                             const float* __restrict__ Wv, const float* __restrict__ Wo) {
    __shared__ float t[32][33];
    int z = blockIdx.z;
    const float* W = (z == 0) ? Wq : (z == 1) ? Wk : (z == 2) ? Wv : Wo;
    int n0 = blockIdx.x * 32, k0 = blockIdx.y * 32;
    int tx = threadIdx.x, ty = threadIdx.y;
    #pragma unroll
    for (int i = 0; i < 4; i++)
        t[ty + 8*i][tx] = W[(size_t)(k0 + ty + 8*i) * DMODEL + n0 + tx];
    __syncthreads();
    #pragma unroll
    for (int i = 0; i < 4; i++) {
        float x = t[tx][ty + 8*i];
        __nv_bfloat16 h, l; split_bf16(x, h, l);
        size_t idx = ((size_t)z * DMODEL + (n0 + ty + 8*i)) * DMODEL + k0 + tx;
        g_wThi[idx] = h; g_wTlo[idx] = l;
    }
}

__global__ void zero_rowsum() {
    size_t i = blockIdx.x * (size_t)blockDim.x + threadIdx.x;
    if (i < (size_t)BH * SEQ) g_rowsum[i] = 0.f;
}

// ---------------------------------------------------------------------------
// Shared GEMM machinery (cp.async double buffer, scalar fragment loads)
// ---------------------------------------------------------------------------
#define STG_STRIDE 40960
#define OFF_AHI 0
#define OFF_ALO 10240
#define OFF_BHI 20480
#define OFF_BLO 30720
#define SMEM_GEMM (2*STG_STRIDE)

__device__ __forceinline__ void gemm_load_stage(uint32_t sb, int s,
        const __nv_bfloat16* Ahi, const __nv_bfloat16* Alo,
        const __nv_bfloat16* Bhi, const __nv_bfloat16* Blo,
        int lda, int ldb, int kt, int tid) {
    uint32_t base = sb + s * STG_STRIDE;
    #pragma unroll
    for (int i = 0; i < 2; i++) {
        int e = tid + i * 256;
        int r = e >> 2, c8 = (e & 3) * 8;
        uint32_t so = r * (SA*2) + c8 * 2;
        size_t ga = (size_t)r * lda + kt + c8;
        size_t gb = (size_t)r * ldb + kt + c8;
        cp16(base + OFF_AHI + so, Ahi + ga);
        cp16(base + OFF_ALO + so, Alo + ga);
        cp16(base + OFF_BHI + so, Bhi + gb);
        cp16(base + OFF_BLO + so, Blo + gb);
    }
}

__device__ __forceinline__ void gemm_compute_stage(char* smem, int s,
        int wm, int wn, int g, int tc, float acc[4][4][4]) {
    const __nv_bfloat16* Ash = (const __nv_bfloat16*)(smem + s*STG_STRIDE + OFF_AHI);
    const __nv_bfloat16* Asl = (const __nv_bfloat16*)(smem + s*STG_STRIDE + OFF_ALO);
    const __nv_bfloat16* Bsh = (const __nv_bfloat16*)(smem + s*STG_STRIDE + OFF_BHI);
    const __nv_bfloat16* Bsl = (const __nv_bfloat16*)(smem + s*STG_STRIDE + OFF_BLO);
    #pragma unroll
    for (int kk = 0; kk < 32; kk += 16) {
        uint32_t ah[4][4], al[4][4];
        #pragma unroll
        for (int mf = 0; mf < 4; mf++) {
            int r0 = (wm + mf*16 + g) * SA + kk + tc*2;
            int r1 = r0 + 8*SA;
            ah[mf][0] = ld32(&Ash[r0]);   ah[mf][1] = ld32(&Ash[r1]);
            ah[mf][2] = ld32(&Ash[r0+8]); ah[mf][3] = ld32(&Ash[r1+8]);
            al[mf][0] = ld32(&Asl[r0]);   al[mf][1] = ld32(&Asl[r1]);
            al[mf][2] = ld32(&Asl[r0+8]); al[mf][3] = ld32(&Asl[r1+8]);
        }
        #pragma unroll
        for (int nf = 0; nf < 4; nf++) {
            int q0 = (wn + nf*8 + g) * SA + kk + tc*2;
            uint32_t bh0 = ld32(&Bsh[q0]), bh1 = ld32(&Bsh[q0+8]);
            uint32_t bl0 = ld32(&Bsl[q0]), bl1 = ld32(&Bsl[q0+8]);
            #pragma unroll
            for (int mf = 0; mf < 4; mf++) {
                mma_bf16(acc[mf][nf], ah[mf][0], ah[mf][1], ah[mf][2], ah[mf][3], bh0, bh1);
                mma_bf16(acc[mf][nf], ah[mf][0], ah[mf][1], ah[mf][2], ah[mf][3], bl0, bl1);
                mma_bf16(acc[mf][nf], al[mf][0], al[mf][1], al[mf][2], al[mf][3], bh0, bh1);
            }
        }
    }
}

// ---------------------------------------------------------------------------
// QKV projection
// ---------------------------------------------------------------------------
__global__ void __launch_bounds__(256) proj_qkv_kernel(
        const float* __restrict__ bq, const float* __restrict__ bk,
        const float* __restrict__ bv) {
    extern __shared__ char smem[];
    uint32_t sb = smem_u32(smem);
    int tid = threadIdx.x, lane = tid & 31, warp = tid >> 5;
    int g = lane >> 2, tc = lane & 3;
    int wm = (warp & 1) * 64, wn = (warp >> 1) * 32;
    int z = blockIdx.z;
    int m0 = blockIdx.y * 128, n0 = blockIdx.x * 128;

    const __nv_bfloat16* Ahi = g_xhi + (size_t)z * MTOT * DMODEL + (size_t)m0 * DMODEL;
    const __nv_bfloat16* Alo = g_xlo + (size_t)z * MTOT * DMODEL + (size_t)m0 * DMODEL;
    const __nv_bfloat16* Bhi = g_wThi + (size_t)z * DMODEL * DMODEL + (size_t)n0 * DMODEL;
    const __nv_bfloat16* Blo = g_wTlo + (size_t)z * DMODEL * DMODEL + (size_t)n0 * DMODEL;
    const float* bias = (z == 0) ? bq : (z == 1) ? bk : bv;

    float acc[4][4][4] = {};
    const int NT = DMODEL / 32;

    gemm_load_stage(sb, 0, Ahi, Alo, Bhi, Blo, DMODEL, DMODEL, 0, tid);
    CP_COMMIT();
    for (int i = 0; i < NT; i++) {
        if (i + 1 < NT) {
            gemm_load_stage(sb, (i+1)&1, Ahi, Alo, Bhi, Blo, DMODEL, DMODEL, (i+1)*32, tid);
            CP_COMMIT();
            CP_WAIT(1);
        } else {
            CP_WAIT(0);
        }
        __syncthreads();
        gemm_compute_stage(smem, i&1, wm, wn, g, tc, acc);
        __syncthreads();
    }

    __nv_bfloat16 *Dh, *Dl;
    if (z == 0) { Dh = g_qhi; Dl = g_qlo; }
    else if (z == 1) { Dh = g_khi; Dl = g_klo; }
    else { Dh = g_vhi; Dl = g_vlo; }

    #pragma unroll
    for (int mf = 0; mf < 4; mf++) {
        #pragma unroll
        for (int rr = 0; rr < 2; rr++) {
            int m = m0 + wm + mf*16 + g + rr*8;
            int b = m >> 11, s = m & (SEQ-1);
            #pragma unroll
            for (int nf = 0; nf < 4; nf++) {
                int n = n0 + wn + nf*8 + tc*2;
                int h = n >> 6, d = n & 63;
                float v0 = acc[mf][nf][rr*2+0] + bias[n];
                float v1 = acc[mf][nf][rr*2+1] + bias[n+1];
                __nv_bfloat16 h0, l0, h1, l1;
                split_bf16(v0, h0, l0); split_bf16(v1, h1, l1);
                size_t base = ((size_t)(b*NHEADS + h) * SEQ + s) * DEPTH + d;
                __nv_bfloat162 hp; hp.x = h0; hp.y = h1;
                __nv_bfloat162 lp; lp.x = l0; lp.y = l1;
                *(__nv_bfloat162*)&Dh[base] = hp;
                *(__nv_bfloat162*)&Dl[base] = lp;
            }
        }
    }
}

// ---------------------------------------------------------------------------
// Transpose V -> vT
// ---------------------------------------------------------------------------
__global__ void __launch_bounds__(256) transpose_v() {
    __shared__ __nv_bfloat16 th[64][66], tl[64][66];
    int bh = blockIdx.z, s0 = blockIdx.x * 64;
    int tid = threadIdx.x;
    #pragma unroll
    for (int i = 0; i < 8; i++) {
        int e = tid + i * 256;
        int r = e >> 5, c2 = (e & 31) * 2;
        size_t gsrc = ((size_t)bh * SEQ + s0 + r) * DEPTH + c2;
        *(uint32_t*)&th[r][c2] = *(const uint32_t*)&g_vhi[gsrc];
        *(uint32_t*)&tl[r][c2] = *(const uint32_t*)&g_vlo[gsrc];
    }
    __syncthreads();
    #pragma unroll
    for (int i = 0; i < 8; i++) {
        int e = tid + i * 256;
        int d = e >> 5, s2 = (e & 31) * 2;
        size_t gdst = ((size_t)bh * DEPTH + d) * SEQ + s0 + s2;
        __nv_bfloat162 ph; ph.x = th[s2][d]; ph.y = th[s2+1][d];
        __nv_bfloat162 pl; pl.x = tl[s2][d]; pl.y = tl[s2+1][d];
        *(__nv_bfloat162*)&g_vThi[gdst] = ph;
        *(__nv_bfloat162*)&g_vTlo[gdst] = pl;
    }
}

// ---------------------------------------------------------------------------
// Scores: writes E = exp(s) (unnormalized) to g_E and accumulates row sums.
// ---------------------------------------------------------------------------
__global__ void __launch_bounds__(256) scores_kernel(const float* __restrict__ mask) {
    extern __shared__ char smem[];
    __shared__ float srow[128];
    uint32_t sb = smem_u32(smem);
    int tid = threadIdx.x, lane = tid & 31, warp = tid >> 5;
    int g = lane >> 2, tc = lane & 3;
    int wm = (warp & 1) * 64, wn = (warp >> 1) * 32;
    int m0 = blockIdx.y * 128, n0 = blockIdx.x * 128;
    int bh = blockIdx.z, b = bh >> 4;

    const __nv_bfloat16* Ahi = g_qhi + ((size_t)bh * SEQ + m0) * DEPTH;
    const __nv_bfloat16* Alo = g_qlo + ((size_t)bh * SEQ + m0) * DEPTH;
    const __nv_bfloat16* Bhi = g_khi + ((size_t)bh * SEQ + n0) * DEPTH;
    const __nv_bfloat16* Blo = g_klo + ((size_t)bh * SEQ + n0) * DEPTH;

    float acc[4][4][4] = {};
    const int NT = DEPTH / 32;

    gemm_load_stage(sb, 0, Ahi, Alo, Bhi, Blo, DEPTH, DEPTH, 0, tid);
    CP_COMMIT();
    for (int i = 0; i < NT; i++) {
        if (i + 1 < NT) {
            gemm_load_stage(sb, (i+1)&1, Ahi, Alo, Bhi, Blo, DEPTH, DEPTH, (i+1)*32, tid);
            CP_COMMIT();
            CP_WAIT(1);
        } else {
            CP_WAIT(0);
        }
        __syncthreads();
        gemm_compute_stage(smem, i&1, wm, wn, g, tc, acc);
        __syncthreads();
    }

    if (tid < 128) srow[tid] = 0.f;
    __syncthreads();

    #pragma unroll
    for (int mf = 0; mf < 4; mf++) {
        #pragma unroll
        for (int rr = 0; rr < 2; rr++) {
            int ml = wm + mf*16 + g + rr*8;
            int m = m0 + ml;
            size_t rowb = ((size_t)bh * SEQ + m) * SEQ;
            float rs = 0.f;
            #pragma unroll
            for (int nf = 0; nf < 4; nf++) {
                int n = n0 + wn + nf*8 + tc*2;
                float2 o;
                o.x = __expf(acc[mf][nf][rr*2+0] * 0.125f + mask[(size_t)b*SEQ + n] * (-1e9f));
                o.y = __expf(acc[mf][nf][rr*2+1] * 0.125f + mask[(size_t)b*SEQ + n + 1] * (-1e9f));
                *(float2*)&g_E[rowb + n] = o;
                rs += o.x + o.y;
            }
            atomicAdd(&srow[ml], rs);
        }
    }
    __syncthreads();
    if (tid < 128) atomicAdd(&g_rowsum[(size_t)bh * SEQ + m0 + tid], srow[tid]);
}

// ---------------------------------------------------------------------------
// Normalize: w = E / rowsum  (off critical path; overlaps with av/proj_out)
// ---------------------------------------------------------------------------
__global__ void __launch_bounds__(256) normalize_kernel(float* __restrict__ w) {
    size_t row = blockIdx.x;
    const float4* src = (const float4*)(g_E + row * SEQ);
    float4* dst = (float4*)(w + row * SEQ);
    float inv = 1.0f / g_rowsum[row];
    int t = threadIdx.x;
    float4 a = src[t];
    a.x *= inv; a.y *= inv; a.z *= inv; a.w *= inv;
    dst[t] = a;
    float4 b = src[t + 256];
    b.x *= inv; b.y *= inv; b.z *= inv; b.w *= inv;
    dst[t + 256] = b;
}

// ---------------------------------------------------------------------------
// AV: reads raw E (fp32) + rowsum; MMA on E; epilogue scaled by 1/rowsum.
// ---------------------------------------------------------------------------
#define AV_AFP(s)  ((s)*20480)
#define AV_BHI(s)  (40960 + (s)*10240)
#define AV_BLO(s)  (40960 + (s)*10240 + 5120)
#define SMEM_AV    61440

__device__ __forceinline__ void av_load_stage(uint32_t sb, int s,
        const float* Aw, const __nv_bfloat16* Bhi, const __nv_bfloat16* Blo,
        int kt, int tid) {
    #pragma unroll
    for (int i = 0; i < 4; i++) {
        int e = tid + i * 256;
        int r = e >> 3, c4 = (e & 7) * 4;
        cp16(sb + AV_AFP(s) + (r * SAF + c4) * 4, Aw + (size_t)r * SEQ + kt + c4);
    }
    {
        int r = tid >> 2, c8 = (tid & 3) * 8;
        uint32_t so = (r * SA + c8) * 2;
        size_t gb = (size_t)r * SEQ + kt + c8;
        cp16(sb + AV_BHI(s) + so, Bhi + gb);
        cp16(sb + AV_BLO(s) + so, Blo + gb);
    }
}

__global__ void __launch_bounds__(256) av_kernel() {
    extern __shared__ char smem[];
    __shared__ float sinv[128];
    uint32_t sb = smem_u32(smem);
    int tid = threadIdx.x, lane = tid & 31, warp = tid >> 5;
    int g = lane >> 2, tc = lane & 3;
    int wm = (warp & 1) * 64, wn = (warp >> 1) * 16;
    int m0 = blockIdx.x * 128;
    int bh = blockIdx.y, b = bh >> 4, h = bh & 15;

    const float* Aw = g_E + ((size_t)bh * SEQ + m0) * SEQ;
    const __nv_bfloat16* Bhi = g_vThi + (size_t)bh * DEPTH * SEQ;
    const __nv_bfloat16* Blo = g_vTlo + (size_t)bh * DEPTH * SEQ;

    if (tid < 128) sinv[tid] = 1.0f / g_rowsum[(size_t)bh * SEQ + m0 + tid];

    float acc[4][2][4] = {};
    const int NT = SEQ / 32;

    av_load_stage(sb, 0, Aw, Bhi, Blo, 0, tid);
    CP_COMMIT();
    for (int i = 0; i < NT; i++) {
        if (i + 1 < NT) {
            av_load_stage(sb, (i+1)&1, Aw, Bhi, Blo, (i+1)*32, tid);
            CP_COMMIT();
            CP_WAIT(1);
        } else {
            CP_WAIT(0);
        }
        __syncthreads();

        int s = i & 1;
        const float* Af = (const float*)(smem + AV_AFP(s));
        const __nv_bfloat16* Bh = (const __nv_bfloat16*)(smem + AV_BHI(s));
        const __nv_bfloat16* Bl = (const __nv_bfloat16*)(smem + AV_BLO(s));

        #pragma unroll
        for (int kk = 0; kk < 32; kk += 16) {
            uint32_t ah[4][4], al[4][4];
            #pragma unroll
            for (int mf = 0; mf < 4; mf++) {
                int r0 = (wm + mf*16 + g) * SAF + kk + tc*2;
                int r1 = r0 + 8*SAF;
                split2(*(const float2*)&Af[r0],   ah[mf][0], al[mf][0]);
                split2(*(const float2*)&Af[r1],   ah[mf][1], al[mf][1]);
                split2(*(const float2*)&Af[r0+8], ah[mf][2], al[mf][2]);
                split2(*(const float2*)&Af[r1+8], ah[mf][3], al[mf][3]);
            }
            #pragma unroll
            for (int nf = 0; nf < 2; nf++) {
                int q0 = (wn + nf*8 + g) * SA + kk + tc*2;
                uint32_t bh0 = ld32(&Bh[q0]), bh1 = ld32(&Bh[q0+8]);
                uint32_t bl0 = ld32(&Bl[q0]), bl1 = ld32(&Bl[q0+8]);
                #pragma unroll
                for (int mf = 0; mf < 4; mf++) {
                    mma_bf16(acc[mf][nf], ah[mf][0], ah[mf][1], ah[mf][2], ah[mf][3], bh0, bh1);
                    mma_bf16(acc[mf][nf], ah[mf][0], ah[mf][1], ah[mf][2], ah[mf][3], bl0, bl1);
                    mma_bf16(acc[mf][nf], al[mf][0], al[mf][1], al[mf][2], al[mf][3], bh0, bh1);
                }
            }
        }
        __syncthreads();
    }

    #pragma unroll
    for (int mf = 0; mf < 4; mf++) {
        #pragma unroll
        for (int rr = 0; rr < 2; rr++) {
            int ml = wm + mf*16 + g + rr*8;
            int s = m0 + ml;
            float inv = sinv[ml];
            size_t base = ((size_t)b * SEQ + s) * DMODEL + h * DEPTH;
            #pragma unroll
            for (int nf = 0; nf < 2; nf++) {
                int d = wn + nf*8 + tc*2;
                float v0 = acc[mf][nf][rr*2+0] * inv;
                float v1 = acc[mf][nf][rr*2+1] * inv;
                __nv_bfloat16 h0, l0, h1, l1;
                split_bf16(v0, h0, l0); split_bf16(v1, h1, l1);
                __nv_bfloat162 hp; hp.x = h0; hp.y = h1;
                __nv_bfloat162 lp; lp.x = l0; lp.y = l1;
                *(__nv_bfloat162*)&g_athi[base + d] = hp;
                *(__nv_bfloat162*)&g_atlo[base + d] = lp;
            }
        }
    }
}

// ---------------------------------------------------------------------------
// Output projection
// ---------------------------------------------------------------------------
__global__ void __launch_bounds__(256) proj_out_kernel(
        const float* __restrict__ bo, float* __restrict__ out) {
    extern __shared__ char smem[];
    uint32_t sb = smem_u32(smem);
    int tid = threadIdx.x, lane = tid & 31, warp = tid >> 5;
    int g = lane >> 2, tc = lane & 3;
    int wm = (warp & 1) * 64, wn = (warp >> 1) * 32;
    int m0 = blockIdx.y * 128, n0 = blockIdx.x * 128;

    const __nv_bfloat16* Ahi = g_athi + (size_t)m0 * DMODEL;
    const __nv_bfloat16* Alo = g_atlo + (size_t)m0 * DMODEL;
    const __nv_bfloat16* Bhi = g_wThi + 3ULL * DMODEL * DMODEL + (size_t)n0 * DMODEL;
    const __nv_bfloat16* Blo = g_wTlo + 3ULL * DMODEL * DMODEL + (size_t)n0 * DMODEL;

    float acc[4][4][4] = {};
    const int NT = DMODEL / 32;

    gemm_load_stage(sb, 0, Ahi, Alo, Bhi, Blo, DMODEL, DMODEL, 0, tid);
    CP_COMMIT();
    for (int i = 0; i < NT; i++) {
        if (i + 1 < NT) {
            gemm_load_stage(sb, (i+1)&1, Ahi, Alo, Bhi, Blo, DMODEL, DMODEL, (i+1)*32, tid);
            CP_COMMIT();
            CP_WAIT(1);
        } else {
            CP_WAIT(0);
        }
        __syncthreads();
        gemm_compute_stage(smem, i&1, wm, wn, g, tc, acc);
        __syncthreads();
    }

    #pragma unroll
    for (int mf = 0; mf < 4; mf++) {
        #pragma unroll
        for (int rr = 0; rr < 2; rr++) {
            int m = m0 + wm + mf*16 + g + rr*8;
            #pragma unroll
            for (int nf = 0; nf < 4; nf++) {
                int n = n0 + wn + nf*8 + tc*2;
                float2 o;
                o.x = acc[mf][nf][rr*2+0] + bo[n];
                o.y = acc[mf][nf][rr*2+1] + bo[n+1];
                *(float2*)&out[(size_t)m * DMODEL + n] = o;
            }
        }
    }
}

// ---------------------------------------------------------------------------
extern "C" void kernel_launch(void* const* d_in, const int* in_sizes, int n_in,
                              void* d_out, int out_size) {
    const float* q    = (const float*)d_in[0];
    const float* k    = (const float*)d_in[1];
    const float* v    = (const float*)d_in[2];
    const float* mask = (const float*)d_in[3];
    const float* Wq   = (const float*)d_in[4];
    const float* bq   = (const float*)d_in[5];
    const float* Wk   = (const float*)d_in[6];
    const float* bk   = (const float*)d_in[7];
    const float* Wv   = (const float*)d_in[8];
    const float* bv   = (const float*)d_in[9];
    const float* Wo   = (const float*)d_in[10];
    const float* bo   = (const float*)d_in[11];

    float* out_main = (float*)d_out;                              // [2,2048,1024]
    float* out_w    = (float*)d_out + (size_t)BS * SEQ * DMODEL;  // [2,16,2048,2048]

    static cudaStream_t s2;
    static cudaEvent_t evA, evT, evS, evN;
    static bool init_done = false;
    if (!init_done) {
        cudaFuncSetAttribute(proj_qkv_kernel, cudaFuncAttributeMaxDynamicSharedMemorySize, SMEM_GEMM);
        cudaFuncSetAttribute(scores_kernel,   cudaFuncAttributeMaxDynamicSharedMemorySize, SMEM_GEMM);
        cudaFuncSetAttribute(av_kernel,       cudaFuncAttributeMaxDynamicSharedMemorySize, SMEM_AV);
        cudaFuncSetAttribute(proj_out_kernel, cudaFuncAttributeMaxDynamicSharedMemorySize, SMEM_GEMM);
        cudaStreamCreateWithFlags(&s2, cudaStreamNonBlocking);
        cudaEventCreateWithFlags(&evA, cudaEventDisableTiming);
        cudaEventCreateWithFlags(&evT, cudaEventDisableTiming);
        cudaEventCreateWithFlags(&evS, cudaEventDisableTiming);
        cudaEventCreateWithFlags(&evN, cudaEventDisableTiming);
        init_done = true;
    }

    prep_inputs<<<2048, 256>>>(q, k, v);
    prep_weights<<<dim3(32, 32, 4), dim3(32, 8)>>>(Wq, Wk, Wv, Wo);
    zero_rowsum<<<(BH*SEQ + 255)/256, 256>>>();

    proj_qkv_kernel<<<dim3(8, 32, 3), 256, SMEM_GEMM>>>(bq, bk, bv);
    cudaEventRecord(evA, 0);

    // fork: transpose_v on s2, overlapping with scores on main
    cudaStreamWaitEvent(s2, evA, 0);
    transpose_v<<<dim3(32, 1, BH), 256, 0, s2>>>();
    cudaEventRecord(evT, s2);

    scores_kernel<<<dim3(16, 16, BH), 256, SMEM_GEMM>>>(mask);
    cudaEventRecord(evS, 0);

    // fork: normalize (E -> w output) on s2, overlapping with av + proj_out
    cudaStreamWaitEvent(s2, evS, 0);
    normalize_kernel<<<BH * SEQ, 256, 0, s2>>>(out_w);
    cudaEventRecord(evN, s2);

    // main: av needs vT (evT) and E/rowsum (in-order after scores)
    cudaStreamWaitEvent(0, evT, 0);
    av_kernel<<<dim3(16, BH), 256, SMEM_AV>>>();

    proj_out_kernel<<<dim3(8, 32), 256, SMEM_GEMM>>>(bo, out_main);

    // join normalize before returning
    cudaStreamWaitEvent(0, evN, 0);
}

// round 17
// speedup vs baseline: 1.1974x; 1.1974x over previous
#include <cuda_runtime.h>
#include <cuda_bf16.h>
#include <cstdint>

#define BS 2
#define SEQ 2048
#define DMODEL 1024
#define NHEADS 16
#define DEPTH 64
#define BH (BS*NHEADS)
#define MTOT (BS*SEQ)
#define SA 40    // bf16 smem row stride
#define SAF 40   // fp32 smem row stride

// ---------------------------------------------------------------------------
// Device scratch
// ---------------------------------------------------------------------------
__device__ __nv_bfloat16 g_xhi[3ULL*MTOT*DMODEL], g_xlo[3ULL*MTOT*DMODEL];
__device__ __nv_bfloat16 g_wThi[4ULL*DMODEL*DMODEL], g_wTlo[4ULL*DMODEL*DMODEL];
__device__ __nv_bfloat16 g_qhi[(size_t)BH*SEQ*DEPTH], g_qlo[(size_t)BH*SEQ*DEPTH];
__device__ __nv_bfloat16 g_khi[(size_t)BH*SEQ*DEPTH], g_klo[(size_t)BH*SEQ*DEPTH];
__device__ __nv_bfloat16 g_vhi[(size_t)BH*SEQ*DEPTH], g_vlo[(size_t)BH*SEQ*DEPTH];
__device__ __nv_bfloat16 g_vThi[(size_t)BH*DEPTH*SEQ], g_vTlo[(size_t)BH*DEPTH*SEQ];
__device__ __nv_bfloat16 g_athi[(size_t)MTOT*DMODEL], g_atlo[(size_t)MTOT*DMODEL];

// ---------------------------------------------------------------------------
__device__ __forceinline__ void split_bf16(float x, __nv_bfloat16& h, __nv_bfloat16& l) {
    h = __float2bfloat16(x);
    l = __float2bfloat16(x - __bfloat162float(h));
}

__device__ __forceinline__ void split2(float2 f, uint32_t& hi, uint32_t& lo) {
    __nv_bfloat162 h = __float22bfloat162_rn(f);
    float2 r;
    r.x = f.x - __bfloat162float(h.x);
    r.y = f.y - __bfloat162float(h.y);
    __nv_bfloat162 l = __float22bfloat162_rn(r);
    hi = *reinterpret_cast<uint32_t*>(&h);
    lo = *reinterpret_cast<uint32_t*>(&l);
}

__device__ __forceinline__ void mma_bf16(float c[4],
        uint32_t a0, uint32_t a1, uint32_t a2, uint32_t a3,
        uint32_t b0, uint32_t b1) {
    asm volatile(
        "mma.sync.aligned.m16n8k16.row.col.f32.bf16.bf16.f32 "
        "{%0,%1,%2,%3}, {%4,%5,%6,%7}, {%8,%9}, {%0,%1,%2,%3};"
        : "+f"(c[0]), "+f"(c[1]), "+f"(c[2]), "+f"(c[3])
        : "r"(a0), "r"(a1), "r"(a2), "r"(a3), "r"(b0), "r"(b1));
}

__device__ __forceinline__ uint32_t ld32(const __nv_bfloat16* p) {
    return *reinterpret_cast<const uint32_t*>(p);
}

__device__ __forceinline__ uint32_t smem_u32(const void* p) {
    uint32_t a;
    asm("{ .reg .u64 t; cvta.to.shared.u64 t, %1; cvt.u32.u64 %0, t; }" : "=r"(a) : "l"(p));
    return a;
}
__device__ __forceinline__ void cp16(uint32_t dst, const void* src) {
    asm volatile("cp.async.cg.shared.global [%0], [%1], 16;" :: "r"(dst), "l"(src));
}
#define CP_COMMIT() asm volatile("cp.async.commit_group;" ::: "memory")
#define CP_WAIT(n)  asm volatile("cp.async.wait_group %0;" :: "n"(n) : "memory")

// ---------------------------------------------------------------------------
// Prep kernels
// ---------------------------------------------------------------------------
__global__ void prep_inputs(const float* __restrict__ q, const float* __restrict__ k,
                            const float* __restrict__ v) {
    const size_t n1 = (size_t)MTOT * DMODEL;
    const size_t n1v = n1 / 4;
    size_t total = 3 * n1v;
    for (size_t i = blockIdx.x * (size_t)blockDim.x + threadIdx.x; i < total;
         i += (size_t)gridDim.x * blockDim.x) {
        size_t seg = i / n1v;
        size_t off = (i - seg * n1v) * 4;
        const float* src = (seg == 0) ? q : (seg == 1) ? k : v;
        float4 f = *(const float4*)(src + off);
        size_t base = seg * n1 + off;
        __nv_bfloat16 h, l;
        split_bf16(f.x, h, l); g_xhi[base+0] = h; g_xlo[base+0] = l;
        split_bf16(f.y, h, l); g_xhi[base+1] = h; g_xlo[base+1] = l;
        split_bf16(f.z, h, l); g_xhi[base+2] = h; g_xlo[base+2] = l;
        split_bf16(f.w, h, l); g_xhi[base+3] = h; g_xlo[base+3] = l;
    }
}

__global__ void prep_weights(const float* __restrict__ Wq, const float* __restrict__ Wk,
                             const float* __restrict__ Wv, const float* __restrict__ Wo) {
    __shared__ float t[32][33];
    int z = blockIdx.z;
    const float* W = (z == 0) ? Wq : (z == 1) ? Wk : (z == 2) ? Wv : Wo;
    int n0 = blockIdx.x * 32, k0 = blockIdx.y * 32;
    int tx = threadIdx.x, ty = threadIdx.y;
    #pragma unroll
    for (int i = 0; i < 4; i++)
        t[ty + 8*i][tx] = W[(size_t)(k0 + ty + 8*i) * DMODEL + n0 + tx];
    __syncthreads();
    #pragma unroll
    for (int i = 0; i < 4; i++) {
        float x = t[tx][ty + 8*i];
        __nv_bfloat16 h, l; split_bf16(x, h, l);
        size_t idx = ((size_t)z * DMODEL + (n0 + ty + 8*i)) * DMODEL + k0 + tx;
        g_wThi[idx] = h; g_wTlo[idx] = l;
    }
}

// ---------------------------------------------------------------------------
// Shared GEMM machinery (cp.async double buffer, scalar fragment loads)
// MMA order: term-major within nf -> RAW distance 4 to each accumulator.
// ---------------------------------------------------------------------------
#define STG_STRIDE 40960
#define OFF_AHI 0
#define OFF_ALO 10240
#define OFF_BHI 20480
#define OFF_BLO 30720
#define SMEM_GEMM (2*STG_STRIDE)

__device__ __forceinline__ void gemm_load_stage(uint32_t sb, int s,
        const __nv_bfloat16* Ahi, const __nv_bfloat16* Alo,
        const __nv_bfloat16* Bhi, const __nv_bfloat16* Blo,
        int lda, int ldb, int kt, int tid) {
    uint32_t base = sb + s * STG_STRIDE;
    #pragma unroll
    for (int i = 0; i < 2; i++) {
        int e = tid + i * 256;
        int r = e >> 2, c8 = (e & 3) * 8;
        uint32_t so = r * (SA*2) + c8 * 2;
        size_t ga = (size_t)r * lda + kt + c8;
        size_t gb = (size_t)r * ldb + kt + c8;
        cp16(base + OFF_AHI + so, Ahi + ga);
        cp16(base + OFF_ALO + so, Alo + ga);
        cp16(base + OFF_BHI + so, Bhi + gb);
        cp16(base + OFF_BLO + so, Blo + gb);
    }
}

__device__ __forceinline__ void gemm_compute_stage(char* smem, int s,
        int wm, int wn, int g, int tc, float acc[4][4][4]) {
    const __nv_bfloat16* Ash = (const __nv_bfloat16*)(smem + s*STG_STRIDE + OFF_AHI);
    const __nv_bfloat16* Asl = (const __nv_bfloat16*)(smem + s*STG_STRIDE + OFF_ALO);
    const __nv_bfloat16* Bsh = (const __nv_bfloat16*)(smem + s*STG_STRIDE + OFF_BHI);
    const __nv_bfloat16* Bsl = (const __nv_bfloat16*)(smem + s*STG_STRIDE + OFF_BLO);
    #pragma unroll
    for (int kk = 0; kk < 32; kk += 16) {
        uint32_t ah[4][4], al[4][4];
        #pragma unroll
        for (int mf = 0; mf < 4; mf++) {
            int r0 = (wm + mf*16 + g) * SA + kk + tc*2;
            int r1 = r0 + 8*SA;
            ah[mf][0] = ld32(&Ash[r0]);   ah[mf][1] = ld32(&Ash[r1]);
            ah[mf][2] = ld32(&Ash[r0+8]); ah[mf][3] = ld32(&Ash[r1+8]);
            al[mf][0] = ld32(&Asl[r0]);   al[mf][1] = ld32(&Asl[r1]);
            al[mf][2] = ld32(&Asl[r0+8]); al[mf][3] = ld32(&Asl[r1+8]);
        }
        #pragma unroll
        for (int nf = 0; nf < 4; nf++) {
            int q0 = (wn + nf*8 + g) * SA + kk + tc*2;
            uint32_t bh0 = ld32(&Bsh[q0]), bh1 = ld32(&Bsh[q0+8]);
            uint32_t bl0 = ld32(&Bsl[q0]), bl1 = ld32(&Bsl[q0+8]);
            // term-major: RAW distance 4 between MMAs on the same accumulator
            #pragma unroll
            for (int mf = 0; mf < 4; mf++)
                mma_bf16(acc[mf][nf], ah[mf][0], ah[mf][1], ah[mf][2], ah[mf][3], bh0, bh1);
            #pragma unroll
            for (int mf = 0; mf < 4; mf++)
                mma_bf16(acc[mf][nf], ah[mf][0], ah[mf][1], ah[mf][2], ah[mf][3], bl0, bl1);
            #pragma unroll
            for (int mf = 0; mf < 4; mf++)
                mma_bf16(acc[mf][nf], al[mf][0], al[mf][1], al[mf][2], al[mf][3], bh0, bh1);
        }
    }
}

// ---------------------------------------------------------------------------
// QKV projection
// ---------------------------------------------------------------------------
__global__ void __launch_bounds__(256) proj_qkv_kernel(
        const float* __restrict__ bq, const float* __restrict__ bk,
        const float* __restrict__ bv) {
    extern __shared__ char smem[];
    uint32_t sb = smem_u32(smem);
    int tid = threadIdx.x, lane = tid & 31, warp = tid >> 5;
    int g = lane >> 2, tc = lane & 3;
    int wm = (warp & 1) * 64, wn = (warp >> 1) * 32;
    int z = blockIdx.z;
    int m0 = blockIdx.y * 128, n0 = blockIdx.x * 128;

    const __nv_bfloat16* Ahi = g_xhi + (size_t)z * MTOT * DMODEL + (size_t)m0 * DMODEL;
    const __nv_bfloat16* Alo = g_xlo + (size_t)z * MTOT * DMODEL + (size_t)m0 * DMODEL;
    const __nv_bfloat16* Bhi = g_wThi + (size_t)z * DMODEL * DMODEL + (size_t)n0 * DMODEL;
    const __nv_bfloat16* Blo = g_wTlo + (size_t)z * DMODEL * DMODEL + (size_t)n0 * DMODEL;
    const float* bias = (z == 0) ? bq : (z == 1) ? bk : bv;

    float acc[4][4][4] = {};
    const int NT = DMODEL / 32;

    gemm_load_stage(sb, 0, Ahi, Alo, Bhi, Blo, DMODEL, DMODEL, 0, tid);
    CP_COMMIT();
    for (int i = 0; i < NT; i++) {
        if (i + 1 < NT) {
            gemm_load_stage(sb, (i+1)&1, Ahi, Alo, Bhi, Blo, DMODEL, DMODEL, (i+1)*32, tid);
            CP_COMMIT();
            CP_WAIT(1);
        } else {
            CP_WAIT(0);
        }
        __syncthreads();
        gemm_compute_stage(smem, i&1, wm, wn, g, tc, acc);
        __syncthreads();
    }

    __nv_bfloat16 *Dh, *Dl;
    if (z == 0) { Dh = g_qhi; Dl = g_qlo; }
    else if (z == 1) { Dh = g_khi; Dl = g_klo; }
    else { Dh = g_vhi; Dl = g_vlo; }

    #pragma unroll
    for (int mf = 0; mf < 4; mf++) {
        #pragma unroll
        for (int rr = 0; rr < 2; rr++) {
            int m = m0 + wm + mf*16 + g + rr*8;
            int b = m >> 11, s = m & (SEQ-1);
            #pragma unroll
            for (int nf = 0; nf < 4; nf++) {
                int n = n0 + wn + nf*8 + tc*2;
                int h = n >> 6, d = n & 63;
                float v0 = acc[mf][nf][rr*2+0] + bias[n];
                float v1 = acc[mf][nf][rr*2+1] + bias[n+1];
                __nv_bfloat16 h0, l0, h1, l1;
                split_bf16(v0, h0, l0); split_bf16(v1, h1, l1);
                size_t base = ((size_t)(b*NHEADS + h) * SEQ + s) * DEPTH + d;
                __nv_bfloat162 hp; hp.x = h0; hp.y = h1;
                __nv_bfloat162 lp; lp.x = l0; lp.y = l1;
                *(__nv_bfloat162*)&Dh[base] = hp;
                *(__nv_bfloat162*)&Dl[base] = lp;
            }
        }
    }
}

// ---------------------------------------------------------------------------
// Transpose V -> vT
// ---------------------------------------------------------------------------
__global__ void __launch_bounds__(256) transpose_v() {
    __shared__ __nv_bfloat16 th[64][66], tl[64][66];
    int bh = blockIdx.z, s0 = blockIdx.x * 64;
    int tid = threadIdx.x;
    #pragma unroll
    for (int i = 0; i < 8; i++) {
        int e = tid + i * 256;
        int r = e >> 5, c2 = (e & 31) * 2;
        size_t gsrc = ((size_t)bh * SEQ + s0 + r) * DEPTH + c2;
        *(uint32_t*)&th[r][c2] = *(const uint32_t*)&g_vhi[gsrc];
        *(uint32_t*)&tl[r][c2] = *(const uint32_t*)&g_vlo[gsrc];
    }
    __syncthreads();
    #pragma unroll
    for (int i = 0; i < 8; i++) {
        int e = tid + i * 256;
        int d = e >> 5, s2 = (e & 31) * 2;
        size_t gdst = ((size_t)bh * DEPTH + d) * SEQ + s0 + s2;
        __nv_bfloat162 ph; ph.x = th[s2][d]; ph.y = th[s2+1][d];
        __nv_bfloat162 pl; pl.x = tl[s2][d]; pl.y = tl[s2+1][d];
        *(__nv_bfloat162*)&g_vThi[gdst] = ph;
        *(__nv_bfloat162*)&g_vTlo[gdst] = pl;
    }
}

// ---------------------------------------------------------------------------
// Scores
// ---------------------------------------------------------------------------
__global__ void __launch_bounds__(256) scores_kernel(
        const float* __restrict__ mask, float* __restrict__ w) {
    extern __shared__ char smem[];
    uint32_t sb = smem_u32(smem);
    int tid = threadIdx.x, lane = tid & 31, warp = tid >> 5;
    int g = lane >> 2, tc = lane & 3;
    int wm = (warp & 1) * 64, wn = (warp >> 1) * 32;
    int m0 = blockIdx.y * 128, n0 = blockIdx.x * 128;
    int bh = blockIdx.z, b = bh >> 4;

    const __nv_bfloat16* Ahi = g_qhi + ((size_t)bh * SEQ + m0) * DEPTH;
    const __nv_bfloat16* Alo = g_qlo + ((size_t)bh * SEQ + m0) * DEPTH;
    const __nv_bfloat16* Bhi = g_khi + ((size_t)bh * SEQ + n0) * DEPTH;
    const __nv_bfloat16* Blo = g_klo + ((size_t)bh * SEQ + n0) * DEPTH;

    float acc[4][4][4] = {};
    const int NT = DEPTH / 32;

    gemm_load_stage(sb, 0, Ahi, Alo, Bhi, Blo, DEPTH, DEPTH, 0, tid);
    CP_COMMIT();
    for (int i = 0; i < NT; i++) {
        if (i + 1 < NT) {
            gemm_load_stage(sb, (i+1)&1, Ahi, Alo, Bhi, Blo, DEPTH, DEPTH, (i+1)*32, tid);
            CP_COMMIT();
            CP_WAIT(1);
        } else {
            CP_WAIT(0);
        }
        __syncthreads();
        gemm_compute_stage(smem, i&1, wm, wn, g, tc, acc);
        __syncthreads();
    }

    #pragma unroll
    for (int mf = 0; mf < 4; mf++) {
        #pragma unroll
        for (int rr = 0; rr < 2; rr++) {
            int m = m0 + wm + mf*16 + g + rr*8;
            size_t rowb = ((size_t)bh * SEQ + m) * SEQ;
            #pragma unroll
            for (int nf = 0; nf < 4; nf++) {
                int n = n0 + wn + nf*8 + tc*2;
                float2 o;
                o.x = acc[mf][nf][rr*2+0] * 0.125f + mask[(size_t)b*SEQ + n] * (-1e9f);
                o.y = acc[mf][nf][rr*2+1] * 0.125f + mask[(size_t)b*SEQ + n + 1] * (-1e9f);
                *(float2*)&w[rowb + n] = o;
            }
        }
    }
}

// ---------------------------------------------------------------------------
// Softmax in place (fp32 only)
// ---------------------------------------------------------------------------
__global__ void __launch_bounds__(256) softmax_kernel(float* __restrict__ w) {
    __shared__ float sred[32];
    size_t row = blockIdx.x;
    float4* p = (float4*)(w + row * SEQ);
    int t = threadIdx.x;

    float4 v0 = p[t];
    float4 v1 = p[t + 256];
    float mx = fmaxf(fmaxf(fmaxf(v0.x, v0.y), fmaxf(v0.z, v0.w)),
                     fmaxf(fmaxf(v1.x, v1.y), fmaxf(v1.z, v1.w)));
    #pragma unroll
    for (int o = 16; o > 0; o >>= 1) mx = fmaxf(mx, __shfl_xor_sync(0xffffffff, mx, o));
    if ((t & 31) == 0) sred[t >> 5] = mx;
    __syncthreads();
    if (t < 32) {
        float m2 = (t < 8) ? sred[t] : -1e30f;
        #pragma unroll
        for (int o = 4; o > 0; o >>= 1) m2 = fmaxf(m2, __shfl_xor_sync(0xffffffff, m2, o));
        if (t == 0) sred[0] = m2;
    }
    __syncthreads();
    mx = sred[0];
    __syncthreads();

    v0.x = __expf(v0.x - mx); v0.y = __expf(v0.y - mx);
    v0.z = __expf(v0.z - mx); v0.w = __expf(v0.w - mx);
    v1.x = __expf(v1.x - mx); v1.y = __expf(v1.y - mx);
    v1.z = __expf(v1.z - mx); v1.w = __expf(v1.w - mx);
    float sum = v0.x + v0.y + v0.z + v0.w + v1.x + v1.y + v1.z + v1.w;
    #pragma unroll
    for (int o = 16; o > 0; o >>= 1) sum += __shfl_xor_sync(0xffffffff, sum, o);
    if ((t & 31) == 0) sred[t >> 5] = sum;
    __syncthreads();
    if (t < 32) {
        float s2 = (t < 8) ? sred[t] : 0.f;
        #pragma unroll
        for (int o = 4; o > 0; o >>= 1) s2 += __shfl_xor_sync(0xffffffff, s2, o);
        if (t == 0) sred[0] = s2;
    }
    __syncthreads();
    float inv = 1.0f / sred[0];

    v0.x *= inv; v0.y *= inv; v0.z *= inv; v0.w *= inv;
    v1.x *= inv; v1.y *= inv; v1.z *= inv; v1.w *= inv;
    p[t] = v0;
    p[t + 256] = v1;
}

// ---------------------------------------------------------------------------
// AV: reads fp32 w; in-register bf16 hi/lo split for A fragments.
// ---------------------------------------------------------------------------
#define AV_AFP(s)  ((s)*20480)
#define AV_BHI(s)  (40960 + (s)*10240)
#define AV_BLO(s)  (40960 + (s)*10240 + 5120)
#define SMEM_AV    61440

__device__ __forceinline__ void av_load_stage(uint32_t sb, int s,
        const float* Aw, const __nv_bfloat16* Bhi, const __nv_bfloat16* Blo,
        int kt, int tid) {
    #pragma unroll
    for (int i = 0; i < 4; i++) {
        int e = tid + i * 256;
        int r = e >> 3, c4 = (e & 7) * 4;
        cp16(sb + AV_AFP(s) + (r * SAF + c4) * 4, Aw + (size_t)r * SEQ + kt + c4);
    }
    {
        int r = tid >> 2, c8 = (tid & 3) * 8;
        uint32_t so = (r * SA + c8) * 2;
        size_t gb = (size_t)r * SEQ + kt + c8;
        cp16(sb + AV_BHI(s) + so, Bhi + gb);
        cp16(sb + AV_BLO(s) + so, Blo + gb);
    }
}

__global__ void __launch_bounds__(256) av_kernel(const float* __restrict__ w) {
    extern __shared__ char smem[];
    uint32_t sb = smem_u32(smem);
    int tid = threadIdx.x, lane = tid & 31, warp = tid >> 5;
    int g = lane >> 2, tc = lane & 3;
    int wm = (warp & 1) * 64, wn = (warp >> 1) * 16;
    int m0 = blockIdx.x * 128;
    int bh = blockIdx.y, b = bh >> 4, h = bh & 15;

    const float* Aw = w + ((size_t)bh * SEQ + m0) * SEQ;
    const __nv_bfloat16* Bhi = g_vThi + (size_t)bh * DEPTH * SEQ;
    const __nv_bfloat16* Blo = g_vTlo + (size_t)bh * DEPTH * SEQ;

    float acc[4][2][4] = {};
    const int NT = SEQ / 32;

    av_load_stage(sb, 0, Aw, Bhi, Blo, 0, tid);
    CP_COMMIT();
    for (int i = 0; i < NT; i++) {
        if (i + 1 < NT) {
            av_load_stage(sb, (i+1)&1, Aw, Bhi, Blo, (i+1)*32, tid);
            CP_COMMIT();
            CP_WAIT(1);
        } else {
            CP_WAIT(0);
        }
        __syncthreads();

        int s = i & 1;
        const float* Af = (const float*)(smem + AV_AFP(s));
        const __nv_bfloat16* Bh = (const __nv_bfloat16*)(smem + AV_BHI(s));
        const __nv_bfloat16* Bl = (const __nv_bfloat16*)(smem + AV_BLO(s));

        #pragma unroll
        for (int kk = 0; kk < 32; kk += 16) {
            uint32_t ah[4][4], al[4][4];
            #pragma unroll
            for (int mf = 0; mf < 4; mf++) {
                int r0 = (wm + mf*16 + g) * SAF + kk + tc*2;
                int r1 = r0 + 8*SAF;
                split2(*(const float2*)&Af[r0],   ah[mf][0], al[mf][0]);
                split2(*(const float2*)&Af[r1],   ah[mf][1], al[mf][1]);
                split2(*(const float2*)&Af[r0+8], ah[mf][2], al[mf][2]);
                split2(*(const float2*)&Af[r1+8], ah[mf][3], al[mf][3]);
            }
            #pragma unroll
            for (int nf = 0; nf < 2; nf++) {
                int q0 = (wn + nf*8 + g) * SA + kk + tc*2;
                uint32_t bh0 = ld32(&Bh[q0]), bh1 = ld32(&Bh[q0+8]);
                uint32_t bl0 = ld32(&Bl[q0]), bl1 = ld32(&Bl[q0+8]);
                // term-major: break accumulator RAW chains
                #pragma unroll
                for (int mf = 0; mf < 4; mf++)
                    mma_bf16(acc[mf][nf], ah[mf][0], ah[mf][1], ah[mf][2], ah[mf][3], bh0, bh1);
                #pragma unroll
                for (int mf = 0; mf < 4; mf++)
                    mma_bf16(acc[mf][nf], ah[mf][0], ah[mf][1], ah[mf][2], ah[mf][3], bl0, bl1);
                #pragma unroll
                for (int mf = 0; mf < 4; mf++)
                    mma_bf16(acc[mf][nf], al[mf][0], al[mf][1], al[mf][2], al[mf][3], bh0, bh1);
            }
        }
        __syncthreads();
    }

    #pragma unroll
    for (int mf = 0; mf < 4; mf++) {
        #pragma unroll
        for (int rr = 0; rr < 2; rr++) {
            int s = m0 + wm + mf*16 + g + rr*8;
            size_t base = ((size_t)b * SEQ + s) * DMODEL + h * DEPTH;
            #pragma unroll
            for (int nf = 0; nf < 2; nf++) {
                int d = wn + nf*8 + tc*2;
                float v0 = acc[mf][nf][rr*2+0];
                float v1 = acc[mf][nf][rr*2+1];
                __nv_bfloat16 h0, l0, h1, l1;
                split_bf16(v0, h0, l0); split_bf16(v1, h1, l1);
                __nv_bfloat162 hp; hp.x = h0; hp.y = h1;
                __nv_bfloat162 lp; lp.x = l0; lp.y = l1;
                *(__nv_bfloat162*)&g_athi[base + d] = hp;
                *(__nv_bfloat162*)&g_atlo[base + d] = lp;
            }
        }
    }
}

// ---------------------------------------------------------------------------
// Output projection
// ---------------------------------------------------------------------------
__global__ void __launch_bounds__(256) proj_out_kernel(
        const float* __restrict__ bo, float* __restrict__ out) {
    extern __shared__ char smem[];
    uint32_t sb = smem_u32(smem);
    int tid = threadIdx.x, lane = tid & 31, warp = tid >> 5;
    int g = lane >> 2, tc = lane & 3;
    int wm = (warp & 1) * 64, wn = (warp >> 1) * 32;
    int m0 = blockIdx.y * 128, n0 = blockIdx.x * 128;

    const __nv_bfloat16* Ahi = g_athi + (size_t)m0 * DMODEL;
    const __nv_bfloat16* Alo = g_atlo + (size_t)m0 * DMODEL;
    const __nv_bfloat16* Bhi = g_wThi + 3ULL * DMODEL * DMODEL + (size_t)n0 * DMODEL;
    const __nv_bfloat16* Blo = g_wTlo + 3ULL * DMODEL * DMODEL + (size_t)n0 * DMODEL;

    float acc[4][4][4] = {};
    const int NT = DMODEL / 32;

    gemm_load_stage(sb, 0, Ahi, Alo, Bhi, Blo, DMODEL, DMODEL, 0, tid);
    CP_COMMIT();
    for (int i = 0; i < NT; i++) {
        if (i + 1 < NT) {
            gemm_load_stage(sb, (i+1)&1, Ahi, Alo, Bhi, Blo, DMODEL, DMODEL, (i+1)*32, tid);
            CP_COMMIT();
            CP_WAIT(1);
        } else {
            CP_WAIT(0);
        }
        __syncthreads();
        gemm_compute_stage(smem, i&1, wm, wn, g, tc, acc);
        __syncthreads();
    }

    #pragma unroll
    for (int mf = 0; mf < 4; mf++) {
        #pragma unroll
        for (int rr = 0; rr < 2; rr++) {
            int m = m0 + wm + mf*16 + g + rr*8;
            #pragma unroll
            for (int nf = 0; nf < 4; nf++) {
                int n = n0 + wn + nf*8 + tc*2;
                float2 o;
                o.x = acc[mf][nf][rr*2+0] + bo[n];
                o.y = acc[mf][nf][rr*2+1] + bo[n+1];
                *(float2*)&out[(size_t)m * DMODEL + n] = o;
            }
        }
    }
}

// ---------------------------------------------------------------------------
extern "C" void kernel_launch(void* const* d_in, const int* in_sizes, int n_in,
                              void* d_out, int out_size) {
    const float* q    = (const float*)d_in[0];
    const float* k    = (const float*)d_in[1];
    const float* v    = (const float*)d_in[2];
    const float* mask = (const float*)d_in[3];
    const float* Wq   = (const float*)d_in[4];
    const float* bq   = (const float*)d_in[5];
    const float* Wk   = (const float*)d_in[6];
    const float* bk   = (const float*)d_in[7];
    const float* Wv   = (const float*)d_in[8];
    const float* bv   = (const float*)d_in[9];
    const float* Wo   = (const float*)d_in[10];
    const float* bo   = (const float*)d_in[11];

    float* out_main = (float*)d_out;                              // [2,2048,1024]
    float* out_w    = (float*)d_out + (size_t)BS * SEQ * DMODEL;  // [2,16,2048,2048]

    static bool attr_done = false;
    if (!attr_done) {
        cudaFuncSetAttribute(proj_qkv_kernel, cudaFuncAttributeMaxDynamicSharedMemorySize, SMEM_GEMM);
        cudaFuncSetAttribute(scores_kernel,   cudaFuncAttributeMaxDynamicSharedMemorySize, SMEM_GEMM);
        cudaFuncSetAttribute(av_kernel,       cudaFuncAttributeMaxDynamicSharedMemorySize, SMEM_AV);
        cudaFuncSetAttribute(proj_out_kernel, cudaFuncAttributeMaxDynamicSharedMemorySize, SMEM_GEMM);
        attr_done = true;
    }

    prep_inputs<<<2048, 256>>>(q, k, v);
    prep_weights<<<dim3(32, 32, 4), dim3(32, 8)>>>(Wq, Wk, Wv, Wo);

    proj_qkv_kernel<<<dim3(8, 32, 3), 256, SMEM_GEMM>>>(bq, bk, bv);
    transpose_v<<<dim3(32, 1, BH), 256>>>();

    scores_kernel<<<dim3(16, 16, BH), 256, SMEM_GEMM>>>(mask, out_w);

    softmax_kernel<<<BH * SEQ, 256>>>(out_w);

    av_kernel<<<dim3(16, BH), 256, SMEM_AV>>>(out_w);

    proj_out_kernel<<<dim3(8, 32), 256, SMEM_GEMM>>>(bo, out_main);
}